// round 16
// baseline (speedup 1.0000x reference)
#include <cuda_runtime.h>
#include <math.h>

// Problem constants
#define Bn   8
#define Cin  128
#define Cout 128
#define Hn   112
#define Wn   112
#define Kk   9
#define HW   (Hn*Wn)            // 12544
#define NPIX (Bn*HW)            // 100352
#define KDIM (Cin*Kk)           // 1152

#define CH   4                  // main: channels per chunk
#define NCH  (Cin/CH)           // 32 chunks
#define KCH  (CH*Kk)            // 36 logical k per chunk
#define KP   40                 // main: padded k per chunk (5 k-steps of 8)
#define KST  44                 // main: smem row stride (words) — conflict-free LDSM

#define SS_BUF_W  (64*KST)      // 2816 words per sample buffer
#define SW_BUF_W  (128*KST)     // 5632 words per weight buffer

#define OCH   8                 // offmask: channels per chunk
#define ONCH  (Cin/OCH)         // 16 chunks
#define OKP   72                // offmask: k per chunk (8*9 = 9 k-steps exactly)

// ---------------- device scratch ----------------
__device__ float  g_xT[(size_t)NPIX*Cin];      // NHWC transpose of x (51.4 MB)
__device__ float4 g_wP4[NCH*Cout*(KP/4)];      // main weights [chunk][o][40], natural k, tf32
__device__ float4 g_owP4[ONCH*32*(OKP/4)];     // offmask weights, permuted tf32
__device__ float4 g_meta_w[NPIX*Kk];           // bilinear tap weights (mask folded)
__device__ int4   g_meta_off[NPIX*Kk];         // clamped plane offsets y*W+x

static __device__ __forceinline__ float to_tf32(float x) {
    float r;
    asm("cvt.rna.tf32.f32 %0, %1;" : "=f"(r) : "f"(x));
    return r;
}
// offmask keeps the frag-pair interleave (LDS.64 path, OKP stride)
static __device__ __forceinline__ int kpos(int kkl) {
    int j = kkl & 7;
    return (kkl >> 3) * 8 + 2 * (j & 3) + (j >> 2);
}
static __device__ __forceinline__ void cp_async16(unsigned smem_dst, const void* gptr) {
    asm volatile("cp.async.cg.shared.global [%0], [%1], 16;"
                 :: "r"(smem_dst), "l"(gptr));
}
#define CP_COMMIT() asm volatile("cp.async.commit_group;" ::: "memory")
#define CP_WAIT0()  asm volatile("cp.async.wait_group 0;" ::: "memory")

#define LDSM_X4(r, addr)                                                        \
    asm volatile("ldmatrix.sync.aligned.m8n8.x4.shared.b16 {%0,%1,%2,%3}, [%4];" \
        : "=r"((r)[0]), "=r"((r)[1]), "=r"((r)[2]), "=r"((r)[3]) : "r"(addr))

// ---------------- kernel 0a: weight prep (tf32 round; main natural-k, offmask permuted) ----------------
__global__ void prep_weights_kernel(const float* __restrict__ w,
                                    const float* __restrict__ ow,
                                    const float* __restrict__ mw) {
    int idx = blockIdx.x * 256 + threadIdx.x;
    if (idx < NCH * Cout * KP) {
        int ch = idx / (Cout * KP);
        int r  = idx - ch * (Cout * KP);
        int o  = r / KP;
        int p  = r - o * KP;                  // natural k position
        float v = 0.f;
        if (p < KCH) {
            int c  = ch * CH + p / 9;
            int kk = p - (p / 9) * 9;
            v = to_tf32(w[(size_t)o * KDIM + c * 9 + kk]);
        }
        ((float*)g_wP4)[idx] = v;
    }
    if (idx < ONCH * 32 * OKP) {              // 36864
        int ch = idx / (32 * OKP);
        int r  = idx - ch * (32 * OKP);
        int n  = r / OKP;
        int p  = r - n * OKP;
        int ks = p >> 3, q = p & 7;
        int j  = (q & 1) * 4 + (q >> 1);
        int kkl = ks * 8 + j;                 // 0..71
        int c   = ch * OCH + kkl / 9;
        int kk  = kkl - (kkl / 9) * 9;
        int gk  = c * 9 + kk;
        float v = 0.f;
        if (n < 18)      v = to_tf32(ow[(size_t)n * KDIM + gk]);
        else if (n < 27) v = to_tf32(mw[(size_t)(n - 18) * KDIM + gk]);
        ((float*)g_owP4)[idx] = v;
    }
}

// ---------------- kernel 0b: NCHW -> NHWC transpose ----------------
__global__ void __launch_bounds__(256)
transpose_kernel(const float* __restrict__ x) {
    __shared__ float s[32][33];
    const int lane = threadIdx.x & 31;
    const int row  = threadIdx.x >> 5;
    const int hw0  = blockIdx.x * 32;
    const int c0   = blockIdx.y * 32;
    const int b    = blockIdx.z;

    const float* xb = x + ((size_t)b * Cin + c0) * HW + hw0;
#pragma unroll
    for (int i = 0; i < 4; i++) {
        int c = row + i * 8;
        s[c][lane] = xb[(size_t)c * HW + lane];
    }
    __syncthreads();
    float* o = g_xT + ((size_t)(b * HW + hw0)) * Cin + c0;
#pragma unroll
    for (int i = 0; i < 4; i++) {
        int hw = row + i * 8;
        o[(size_t)hw * Cin + lane] = s[lane][hw];
    }
}

// ---------------- kernel 1: offmask conv via TF32 MMA -> sampling metadata ----------------
__global__ void __launch_bounds__(256)
offmask_kernel(const float* __restrict__ ob,
               const float* __restrict__ mb) {
    __shared__ __align__(16) float s_x[64 * OKP];    // 18432 B
    __shared__ __align__(16) float s_ww[32 * OKP];   //  9216 B
    __shared__ float s_r[64 * 32];                   //  8192 B

    const int tid  = threadIdx.x;
    const int pix0 = blockIdx.x * 64;
    const int b    = pix0 / HW;
    const int bHW  = b * HW;

    const int lane = tid & 31;
    const int wid  = tid >> 5;
    const int m0   = (wid & 3) * 16;
    const int n0   = (wid >> 2) * 16;
    const int arow = lane >> 2;
    const int acol = lane & 3;
    const int sp   = tid >> 2;              // pixel 0..63
    const int kq   = tid & 3;               // tap phase

    const int remS = (pix0 + sp) - bHW;
    const int hS   = remS / Wn;
    const int wS   = remS - hS * Wn;

    float acc[2][4];
#pragma unroll
    for (int na = 0; na < 2; na++)
#pragma unroll
        for (int q = 0; q < 4; q++) acc[na][q] = 0.f;

    for (int ch = 0; ch < ONCH; ch++) {
        const int c0 = ch * OCH;
        const float4* wp = g_owP4 + ch * 576;
        for (int i = tid; i < 576; i += 256)
            ((float4*)s_ww)[i] = __ldg(wp + i);

#pragma unroll
        for (int j = 0; j < 3; j++) {
            int tk = (j < 2) ? (kq + 4 * j) : 8;
            if (j == 2 && kq != 0) break;
            int di = tk / 3, dj = tk - di * 3;
            int y = hS - 1 + di, xx = wS - 1 + dj;
            bool ok = ((unsigned)y < (unsigned)Hn) && ((unsigned)xx < (unsigned)Wn);
            float4 va = make_float4(0, 0, 0, 0), vb = make_float4(0, 0, 0, 0);
            if (ok) {
                const float4* r = (const float4*)(g_xT
                    + ((size_t)(bHW + y * Wn + xx)) * Cin + c0);
                va = __ldg(r);
                vb = __ldg(r + 1);
            }
            s_x[sp * OKP + kpos(0 * 9 + tk)] = to_tf32(va.x);
            s_x[sp * OKP + kpos(1 * 9 + tk)] = to_tf32(va.y);
            s_x[sp * OKP + kpos(2 * 9 + tk)] = to_tf32(va.z);
            s_x[sp * OKP + kpos(3 * 9 + tk)] = to_tf32(va.w);
            s_x[sp * OKP + kpos(4 * 9 + tk)] = to_tf32(vb.x);
            s_x[sp * OKP + kpos(5 * 9 + tk)] = to_tf32(vb.y);
            s_x[sp * OKP + kpos(6 * 9 + tk)] = to_tf32(vb.z);
            s_x[sp * OKP + kpos(7 * 9 + tk)] = to_tf32(vb.w);
        }
        __syncthreads();

#pragma unroll
        for (int ks = 0; ks < 9; ks++) {
            const int ko = ks * 8 + 2 * acol;
            const int abase = (m0 + arow) * OKP + ko;
            uint2 lo = *(const uint2*)(s_x + abase);
            uint2 hi = *(const uint2*)(s_x + abase + 8 * OKP);
#pragma unroll
            for (int na = 0; na < 2; na++) {
                uint2 bb = *(const uint2*)(s_ww + (n0 + na * 8 + arow) * OKP + ko);
                asm volatile(
                    "mma.sync.aligned.m16n8k8.row.col.f32.tf32.tf32.f32 "
                    "{%0,%1,%2,%3}, {%4,%5,%6,%7}, {%8,%9}, {%0,%1,%2,%3};"
                    : "+f"(acc[na][0]), "+f"(acc[na][1]),
                      "+f"(acc[na][2]), "+f"(acc[na][3])
                    : "r"(lo.x), "r"(hi.x), "r"(lo.y), "r"(hi.y),
                      "r"(bb.x), "r"(bb.y));
            }
        }
        __syncthreads();
    }

#pragma unroll
    for (int na = 0; na < 2; na++) {
        int col = n0 + na * 8 + 2 * acol;
        int r0 = m0 + arow, r1 = r0 + 8;
        s_r[r0 * 32 + col]     = acc[na][0];
        s_r[r0 * 32 + col + 1] = acc[na][1];
        s_r[r1 * 32 + col]     = acc[na][2];
        s_r[r1 * 32 + col + 1] = acc[na][3];
    }
    __syncthreads();

    const int px = tid >> 2;
    const int ph = tid & 3;
    const int pix = pix0 + px;
    const int rem = pix - bHW;
    const int h  = rem / Wn;
    const int wc = rem - h * Wn;
    const float* rr = s_r + px * 32;

#pragma unroll
    for (int t = 0; t < 3; t++) {
        int k = ph + 4 * t;
        if (k >= 9) break;
        float dy = rr[2 * k]     + __ldg(ob + 2 * k);
        float dx = rr[2 * k + 1] + __ldg(ob + 2 * k + 1);
        float mraw = rr[18 + k]  + __ldg(mb + k);
        float mval = 2.f / (1.f + expf(-mraw));
        int ki = k / 3, kj = k - ki * 3;
        float ys = (float)(h - 1 + ki) + dy;
        float xs = (float)(wc - 1 + kj) + dx;
        float y0f = floorf(ys), x0f = floorf(xs);
        float ly = ys - y0f, lx = xs - x0f;
        int y0 = (int)y0f, x0 = (int)x0f;
        int y1 = y0 + 1, x1 = x0 + 1;
        float vy0 = ((unsigned)y0 < (unsigned)Hn) ? 1.f : 0.f;
        float vy1 = ((unsigned)y1 < (unsigned)Hn) ? 1.f : 0.f;
        float vx0 = ((unsigned)x0 < (unsigned)Wn) ? 1.f : 0.f;
        float vx1 = ((unsigned)x1 < (unsigned)Wn) ? 1.f : 0.f;
        float w00 = mval * (1.f - ly) * (1.f - lx) * vy0 * vx0;
        float w01 = mval * (1.f - ly) * lx          * vy0 * vx1;
        float w10 = mval * ly          * (1.f - lx) * vy1 * vx0;
        float w11 = mval * ly          * lx          * vy1 * vx1;
        int y0c = min(max(y0, 0), Hn - 1), y1c = min(max(y1, 0), Hn - 1);
        int x0c = min(max(x0, 0), Wn - 1), x1c = min(max(x1, 0), Wn - 1);
        int oy0 = y0c * Wn, oy1 = y1c * Wn;
        g_meta_w[pix * 9 + k]   = make_float4(w00, w01, w10, w11);
        g_meta_off[pix * 9 + k] = make_int4(oy0 + x0c, oy0 + x1c, oy1 + x0c, oy1 + x1c);
    }
}

// natural k order sample store (stride KST=44)
#define SAMP_STORE(dst, k, t0, t1, t2, t3, wv)                                  \
    do {                                                                        \
        (dst)[sp * KST + 0 * 9 + (k)] =                                         \
            to_tf32((wv).x * (t0).x + (wv).y * (t1).x + (wv).z * (t2).x + (wv).w * (t3).x); \
        (dst)[sp * KST + 1 * 9 + (k)] =                                         \
            to_tf32((wv).x * (t0).y + (wv).y * (t1).y + (wv).z * (t2).y + (wv).w * (t3).y); \
        (dst)[sp * KST + 2 * 9 + (k)] =                                         \
            to_tf32((wv).x * (t0).z + (wv).y * (t1).z + (wv).z * (t2).z + (wv).w * (t3).z); \
        (dst)[sp * KST + 3 * 9 + (k)] =                                         \
            to_tf32((wv).x * (t0).w + (wv).y * (t1).w + (wv).z * (t2).w + (wv).w * (t3).w); \
    } while (0)

#define GATHER4(dst, base, ov)                                                        \
    do {                                                                              \
        (dst)[0] = __ldg((const float4*)((base) + ((size_t)(bHW + (ov).x)) * Cin));   \
        (dst)[1] = __ldg((const float4*)((base) + ((size_t)(bHW + (ov).y)) * Cin));   \
        (dst)[2] = __ldg((const float4*)((base) + ((size_t)(bHW + (ov).z)) * Cin));   \
        (dst)[3] = __ldg((const float4*)((base) + ((size_t)(bHW + (ov).w)) * Cin));   \
    } while (0)

// ---------------- kernel 2: pipelined fused sample + TF32 MMA (ldmatrix fragments) ----------------
__global__ void __launch_bounds__(256, 2)
main_kernel(const float* __restrict__ bias,
            float* __restrict__ out) {
    extern __shared__ char dyn[];
    float*  s_s  = (float*)dyn;                          // 2 x 64*44*4  = 22528 B
    float*  s_w  = (float*)(dyn + 22528);                // 2 x 128*44*4 = 45056 B

    const int tid  = threadIdx.x;
    const int pix0 = blockIdx.x * 64;
    const int b    = pix0 / HW;
    const int bHW  = b * HW;
    const int hw0  = pix0 - bHW;

    const int lane = tid & 31;
    const int wid  = tid >> 5;
    const int m0   = (wid & 1) * 32;
    const int n0   = (wid >> 1) * 32;
    const int arow = lane >> 2;
    const int acol = lane & 3;
    const int sp   = tid >> 2;            // pixel 0..63
    const int kq   = tid & 3;             // k phase 0..3

    // ---- hoist this thread's sampling metadata into registers (once) ----
    const int mbase = (pix0 + sp) * 9;
    int4   mo0 = __ldg(g_meta_off + mbase + kq);
    int4   mo1 = __ldg(g_meta_off + mbase + kq + 4);
    float4 mw0 = __ldg(g_meta_w   + mbase + kq);
    float4 mw1 = __ldg(g_meta_w   + mbase + kq + 4);
    int4   mo2 = make_int4(0, 0, 0, 0);
    float4 mw2 = make_float4(0, 0, 0, 0);
    if (kq == 0) {
        mo2 = __ldg(g_meta_off + mbase + 8);
        mw2 = __ldg(g_meta_w   + mbase + 8);
    }

    // zero pad lanes (k 36..39, natural positions) in both s_s buffers
    for (int i = tid; i < 512; i += 256) {
        int bu = i >> 8, r = i & 255;
        int p = r >> 2, pj = r & 3;
        s_s[bu * SS_BUF_W + p * KST + 36 + pj] = 0.f;
    }

    const unsigned dyn_u = (unsigned)__cvta_generic_to_shared(dyn);
    const unsigned ss_u  = dyn_u;
    const unsigned sw_u  = dyn_u + 22528;

    // ldmatrix lane-address constants
    const int m2 = lane >> 3;             // matrix index 0..3
    const int l7 = lane & 7;              // row within matrix
    const unsigned aoff0 = ((m0 + (m2 & 1) * 8 + l7) * KST + (m2 >> 1) * 4) * 4;
    const unsigned aoff1 = aoff0 + 16 * KST * 4;
    const unsigned boff0 = ((n0 + (m2 >> 1) * 8 + l7) * KST + (m2 & 1) * 4) * 4;
    const unsigned boff1 = boff0 + 16 * KST * 4;

    float acc[2][4][4];
#pragma unroll
    for (int ma = 0; ma < 2; ma++)
#pragma unroll
        for (int na = 0; na < 4; na++)
#pragma unroll
            for (int q = 0; q < 4; q++) acc[ma][na][q] = 0.f;

    // ---- prologue: stage chunk 0 into buffer 0 ----
    {
        const float4* wp = g_wP4;
#pragma unroll
        for (int j = 0; j < 5; j++) {
            int idx = tid + j * 256;                 // 0..1279
            int o = idx / 10, r = idx - o * 10;      // o row, 16B chunk r
            cp_async16(sw_u + (o * KST + r * 4) * 4, wp + idx);
        }
        CP_COMMIT();

        float4 t[4];
        GATHER4(t, g_xT, mo0);
        SAMP_STORE(s_s, kq, t[0], t[1], t[2], t[3], mw0);
        GATHER4(t, g_xT, mo1);
        SAMP_STORE(s_s, kq + 4, t[0], t[1], t[2], t[3], mw1);
        if (kq == 0) {
            GATHER4(t, g_xT, mo2);
            SAMP_STORE(s_s, 8, t[0], t[1], t[2], t[3], mw2);
        }
        CP_WAIT0();
    }
    __syncthreads();

    for (int i = 0; i < NCH; i++) {
        const int cur = i & 1, nxt = cur ^ 1;
        const bool pf = (i + 1) < NCH;

        // ---- 1. prefetch chunk i+1: weights via cp.async, taps into regs ----
        float4 tp[2][4];
        if (pf) {
            const float4* wp = g_wP4 + (size_t)(i + 1) * (Cout * KP / 4);
            const unsigned swn_u = sw_u + nxt * 22528;
#pragma unroll
            for (int j = 0; j < 5; j++) {
                int idx = tid + j * 256;
                int o = idx / 10, r = idx - o * 10;
                cp_async16(swn_u + (o * KST + r * 4) * 4, wp + idx);
            }
            CP_COMMIT();
            const float* base = g_xT + (i + 1) * CH;
            GATHER4(tp[0], base, mo0);
            GATHER4(tp[1], base, mo1);
        }

        // ---- 2. MMA on chunk i (ldmatrix fragments) ----
        {
            const unsigned ssb = ss_u + cur * 11264;
            const unsigned swb = sw_u + cur * 22528;
#pragma unroll
            for (int ks = 0; ks < 5; ks++) {
                const unsigned kof = ks * 32;
                unsigned a0[4], a1[4], bb0[4], bb1[4];
                LDSM_X4(a0, ssb + aoff0 + kof);
                LDSM_X4(a1, ssb + aoff1 + kof);
                LDSM_X4(bb0, swb + boff0 + kof);
                LDSM_X4(bb1, swb + boff1 + kof);
#pragma unroll
                for (int na = 0; na < 4; na++) {
                    const unsigned* bb = (na < 2) ? bb0 : bb1;
                    unsigned bx = bb[(na & 1) * 2], by = bb[(na & 1) * 2 + 1];
                    asm volatile(
                        "mma.sync.aligned.m16n8k8.row.col.f32.tf32.tf32.f32 "
                        "{%0,%1,%2,%3}, {%4,%5,%6,%7}, {%8,%9}, {%0,%1,%2,%3};"
                        : "+f"(acc[0][na][0]), "+f"(acc[0][na][1]),
                          "+f"(acc[0][na][2]), "+f"(acc[0][na][3])
                        : "r"(a0[0]), "r"(a0[1]), "r"(a0[2]), "r"(a0[3]),
                          "r"(bx), "r"(by));
                    asm volatile(
                        "mma.sync.aligned.m16n8k8.row.col.f32.tf32.tf32.f32 "
                        "{%0,%1,%2,%3}, {%4,%5,%6,%7}, {%8,%9}, {%0,%1,%2,%3};"
                        : "+f"(acc[1][na][0]), "+f"(acc[1][na][1]),
                          "+f"(acc[1][na][2]), "+f"(acc[1][na][3])
                        : "r"(a1[0]), "r"(a1[1]), "r"(a1[2]), "r"(a1[3]),
                          "r"(bx), "r"(by));
                }
            }
        }

        // ---- 3. writeback chunk i+1 samples; wait weights; barrier ----
        if (pf) {
            float* ssn = s_s + nxt * SS_BUF_W;
            SAMP_STORE(ssn, kq,     tp[0][0], tp[0][1], tp[0][2], tp[0][3], mw0);
            SAMP_STORE(ssn, kq + 4, tp[1][0], tp[1][1], tp[1][2], tp[1][3], mw1);
            if (kq == 0) {     // inline task k=8
                const float* base = g_xT + (i + 1) * CH;
                float4 t[4];
                GATHER4(t, base, mo2);
                SAMP_STORE(ssn, 8, t[0], t[1], t[2], t[3], mw2);
            }
            CP_WAIT0();
        }
        __syncthreads();
    }

    // ---- epilogue: fp32 bias add + stores ----
#pragma unroll
    for (int ma = 0; ma < 2; ma++) {
        int prow = hw0 + m0 + ma * 16 + arow;
#pragma unroll
        for (int na = 0; na < 4; na++) {
            int o = n0 + na * 8 + 2 * acol;
            float b0 = __ldg(bias + o);
            float b1 = __ldg(bias + o + 1);
            float* p0 = out + ((size_t)b * Cout + o) * HW + prow;
            float* p1 = p0 + HW;
            p0[0] = acc[ma][na][0] + b0;
            p1[0] = acc[ma][na][1] + b1;
            p0[8] = acc[ma][na][2] + b0;
            p1[8] = acc[ma][na][3] + b1;
        }
    }
}

// ---------------- launcher ----------------
extern "C" void kernel_launch(void* const* d_in, const int* in_sizes, int n_in,
                              void* d_out, int out_size) {
    const float* x        = (const float*)d_in[0];
    const float* offset_w = (const float*)d_in[1];
    const float* offset_b = (const float*)d_in[2];
    const float* mod_w    = (const float*)d_in[3];
    const float* mod_b    = (const float*)d_in[4];
    const float* w        = (const float*)d_in[5];
    const float* bias     = (const float*)d_in[6];
    float* out = (float*)d_out;

    const int SMEM = 22528 + 45056;   // 67584 B
    cudaFuncSetAttribute(main_kernel, cudaFuncAttributeMaxDynamicSharedMemorySize, SMEM);

    prep_weights_kernel<<<(NCH * Cout * KP + 255) / 256, 256>>>(w, offset_w, mod_w);
    transpose_kernel<<<dim3(HW / 32, Cin / 32, Bn), 256>>>(x);
    offmask_kernel<<<NPIX / 64, 256>>>(offset_b, mod_b);
    main_kernel<<<NPIX / 64, 256, SMEM>>>(bias, out);
}

// round 17
// speedup vs baseline: 1.6014x; 1.6014x over previous
#include <cuda_runtime.h>
#include <cuda_fp16.h>
#include <math.h>

// Problem constants
#define Bn   8
#define Cin  128
#define Cout 128
#define Hn   112
#define Wn   112
#define Kk   9
#define HW   (Hn*Wn)            // 12544
#define NPIX (Bn*HW)            // 100352
#define KDIM (Cin*Kk)           // 1152

#define CH   8                  // main: channels per chunk (fp16: 16B per gather)
#define NCH  (Cin/CH)           // 16 chunks
#define KCH  (CH*Kk)            // 72 logical k per chunk (tap-major: p = tk*8 + c)
#define KP   80                 // padded k per chunk (5 k16-steps)
#define KST  88                 // smem row stride (halfs) = 176B, conflict-free LDSM

#define SS_BUF_H  (64*KST)      // 5632 halfs  = 11264 B per sample buffer
#define SW_BUF_H  (128*KST)     // 11264 halfs = 22528 B per weight buffer

#define OCH   8                 // offmask: channels per chunk
#define ONCH  (Cin/OCH)         // 16 chunks
#define OKP   72                // offmask: k per chunk

// ---------------- device scratch ----------------
__device__ __half g_xT[(size_t)NPIX*Cin];      // NHWC fp16 x (25.7 MB)
__device__ __half g_wH[NCH*Cout*KP];           // main weights fp16, tap-major k
__device__ float4 g_owP4[ONCH*32*(OKP/4)];     // offmask weights, permuted tf32
__device__ float4 g_meta_w[NPIX*Kk];           // bilinear tap weights (mask folded)
__device__ int4   g_meta_off[NPIX*Kk];         // clamped plane offsets y*W+x

static __device__ __forceinline__ float to_tf32(float x) {
    float r;
    asm("cvt.rna.tf32.f32 %0, %1;" : "=f"(r) : "f"(x));
    return r;
}
// offmask frag-pair interleave (tf32 LDS.64 path)
static __device__ __forceinline__ int kpos(int kkl) {
    int j = kkl & 7;
    return (kkl >> 3) * 8 + 2 * (j & 3) + (j >> 2);
}
static __device__ __forceinline__ void cp_async16(unsigned smem_dst, const void* gptr) {
    asm volatile("cp.async.cg.shared.global [%0], [%1], 16;"
                 :: "r"(smem_dst), "l"(gptr));
}
#define CP_COMMIT() asm volatile("cp.async.commit_group;" ::: "memory")
#define CP_WAIT0()  asm volatile("cp.async.wait_group 0;" ::: "memory")

#define LDSM_X4(r, addr)                                                        \
    asm volatile("ldmatrix.sync.aligned.m8n8.x4.shared.b16 {%0,%1,%2,%3}, [%4];" \
        : "=r"((r)[0]), "=r"((r)[1]), "=r"((r)[2]), "=r"((r)[3]) : "r"(addr))

// half c (0..7) of a uint4 as float
static __device__ __forceinline__ float hget(const uint4& t, int c) {
    unsigned v = (&t.x)[c >> 1];
    __half h = __ushort_as_half((unsigned short)((c & 1) ? (v >> 16) : (v & 0xffff)));
    return __half2float(h);
}

// ---------------- kernel 0a: weight prep ----------------
__global__ void prep_weights_kernel(const float* __restrict__ w,
                                    const float* __restrict__ ow,
                                    const float* __restrict__ mw) {
    int idx = blockIdx.x * 256 + threadIdx.x;
    if (idx < NCH * Cout * KP) {              // 163840
        int ch = idx / (Cout * KP);
        int r  = idx - ch * (Cout * KP);
        int o  = r / KP;
        int p  = r - o * KP;                  // tap-major: p = tk*8 + c
        int tk = p >> 3, c = p & 7;
        float v = 0.f;
        if (tk < 9)
            v = w[(size_t)o * KDIM + (ch * CH + c) * 9 + tk];
        g_wH[idx] = __float2half_rn(v);
    }
    if (idx < ONCH * 32 * OKP) {              // 36864
        int ch = idx / (32 * OKP);
        int r  = idx - ch * (32 * OKP);
        int n  = r / OKP;
        int p  = r - n * OKP;
        int ks = p >> 3, q = p & 7;
        int j  = (q & 1) * 4 + (q >> 1);
        int kkl = ks * 8 + j;
        int c   = ch * OCH + kkl / 9;
        int kk  = kkl - (kkl / 9) * 9;
        int gk  = c * 9 + kk;
        float v = 0.f;
        if (n < 18)      v = to_tf32(ow[(size_t)n * KDIM + gk]);
        else if (n < 27) v = to_tf32(mw[(size_t)(n - 18) * KDIM + gk]);
        ((float*)g_owP4)[idx] = v;
    }
}

// ---------------- kernel 0b: NCHW fp32 -> NHWC fp16 transpose ----------------
__global__ void __launch_bounds__(256)
transpose_kernel(const float* __restrict__ x) {
    __shared__ float s[32][33];
    const int lane = threadIdx.x & 31;
    const int row  = threadIdx.x >> 5;
    const int hw0  = blockIdx.x * 32;
    const int c0   = blockIdx.y * 32;
    const int b    = blockIdx.z;

    const float* xb = x + ((size_t)b * Cin + c0) * HW + hw0;
#pragma unroll
    for (int i = 0; i < 4; i++) {
        int c = row + i * 8;
        s[c][lane] = xb[(size_t)c * HW + lane];
    }
    __syncthreads();
    __half* o = g_xT + ((size_t)(b * HW + hw0)) * Cin + c0;
#pragma unroll
    for (int i = 0; i < 4; i++) {
        int hw = row + i * 8;
        o[(size_t)hw * Cin + lane] = __float2half_rn(s[lane][hw]);
    }
}

// ---------------- kernel 1: offmask conv via TF32 MMA -> sampling metadata ----------------
__global__ void __launch_bounds__(256)
offmask_kernel(const float* __restrict__ ob,
               const float* __restrict__ mb) {
    __shared__ __align__(16) float s_x[64 * OKP];    // 18432 B
    __shared__ __align__(16) float s_ww[32 * OKP];   //  9216 B
    __shared__ float s_r[64 * 32];                   //  8192 B

    const int tid  = threadIdx.x;
    const int pix0 = blockIdx.x * 64;
    const int b    = pix0 / HW;
    const int bHW  = b * HW;

    const int lane = tid & 31;
    const int wid  = tid >> 5;
    const int m0   = (wid & 3) * 16;
    const int n0   = (wid >> 2) * 16;
    const int arow = lane >> 2;
    const int acol = lane & 3;
    const int sp   = tid >> 2;              // pixel 0..63
    const int kq   = tid & 3;               // tap phase

    const int remS = (pix0 + sp) - bHW;
    const int hS   = remS / Wn;
    const int wS   = remS - hS * Wn;

    float acc[2][4];
#pragma unroll
    for (int na = 0; na < 2; na++)
#pragma unroll
        for (int q = 0; q < 4; q++) acc[na][q] = 0.f;

    for (int ch = 0; ch < ONCH; ch++) {
        const int c0 = ch * OCH;
        const float4* wp = g_owP4 + ch * 576;
        for (int i = tid; i < 576; i += 256)
            ((float4*)s_ww)[i] = __ldg(wp + i);

#pragma unroll
        for (int j = 0; j < 3; j++) {
            int tk = (j < 2) ? (kq + 4 * j) : 8;
            if (j == 2 && kq != 0) break;
            int di = tk / 3, dj = tk - di * 3;
            int y = hS - 1 + di, xx = wS - 1 + dj;
            bool ok = ((unsigned)y < (unsigned)Hn) && ((unsigned)xx < (unsigned)Wn);
            uint4 va = make_uint4(0, 0, 0, 0);
            if (ok)
                va = __ldg((const uint4*)(g_xT + ((size_t)(bHW + y * Wn + xx)) * Cin + c0));
#pragma unroll
            for (int c = 0; c < 8; c++)
                s_x[sp * OKP + kpos(c * 9 + tk)] = hget(va, c);  // fp16 exact in tf32
        }
        __syncthreads();

#pragma unroll
        for (int ks = 0; ks < 9; ks++) {
            const int ko = ks * 8 + 2 * acol;
            const int abase = (m0 + arow) * OKP + ko;
            uint2 lo = *(const uint2*)(s_x + abase);
            uint2 hi = *(const uint2*)(s_x + abase + 8 * OKP);
#pragma unroll
            for (int na = 0; na < 2; na++) {
                uint2 bb = *(const uint2*)(s_ww + (n0 + na * 8 + arow) * OKP + ko);
                asm volatile(
                    "mma.sync.aligned.m16n8k8.row.col.f32.tf32.tf32.f32 "
                    "{%0,%1,%2,%3}, {%4,%5,%6,%7}, {%8,%9}, {%0,%1,%2,%3};"
                    : "+f"(acc[na][0]), "+f"(acc[na][1]),
                      "+f"(acc[na][2]), "+f"(acc[na][3])
                    : "r"(lo.x), "r"(hi.x), "r"(lo.y), "r"(hi.y),
                      "r"(bb.x), "r"(bb.y));
            }
        }
        __syncthreads();
    }

#pragma unroll
    for (int na = 0; na < 2; na++) {
        int col = n0 + na * 8 + 2 * acol;
        int r0 = m0 + arow, r1 = r0 + 8;
        s_r[r0 * 32 + col]     = acc[na][0];
        s_r[r0 * 32 + col + 1] = acc[na][1];
        s_r[r1 * 32 + col]     = acc[na][2];
        s_r[r1 * 32 + col + 1] = acc[na][3];
    }
    __syncthreads();

    const int px = tid >> 2;
    const int ph = tid & 3;
    const int pix = pix0 + px;
    const int rem = pix - bHW;
    const int h  = rem / Wn;
    const int wc = rem - h * Wn;
    const float* rr = s_r + px * 32;

#pragma unroll
    for (int t = 0; t < 3; t++) {
        int k = ph + 4 * t;
        if (k >= 9) break;
        float dy = rr[2 * k]     + __ldg(ob + 2 * k);
        float dx = rr[2 * k + 1] + __ldg(ob + 2 * k + 1);
        float mraw = rr[18 + k]  + __ldg(mb + k);
        float mval = 2.f / (1.f + expf(-mraw));
        int ki = k / 3, kj = k - ki * 3;
        float ys = (float)(h - 1 + ki) + dy;
        float xs = (float)(wc - 1 + kj) + dx;
        float y0f = floorf(ys), x0f = floorf(xs);
        float ly = ys - y0f, lx = xs - x0f;
        int y0 = (int)y0f, x0 = (int)x0f;
        int y1 = y0 + 1, x1 = x0 + 1;
        float vy0 = ((unsigned)y0 < (unsigned)Hn) ? 1.f : 0.f;
        float vy1 = ((unsigned)y1 < (unsigned)Hn) ? 1.f : 0.f;
        float vx0 = ((unsigned)x0 < (unsigned)Wn) ? 1.f : 0.f;
        float vx1 = ((unsigned)x1 < (unsigned)Wn) ? 1.f : 0.f;
        float w00 = mval * (1.f - ly) * (1.f - lx) * vy0 * vx0;
        float w01 = mval * (1.f - ly) * lx          * vy0 * vx1;
        float w10 = mval * ly          * (1.f - lx) * vy1 * vx0;
        float w11 = mval * ly          * lx          * vy1 * vx1;
        int y0c = min(max(y0, 0), Hn - 1), y1c = min(max(y1, 0), Hn - 1);
        int x0c = min(max(x0, 0), Wn - 1), x1c = min(max(x1, 0), Wn - 1);
        int oy0 = y0c * Wn, oy1 = y1c * Wn;
        g_meta_w[pix * 9 + k]   = make_float4(w00, w01, w10, w11);
        g_meta_off[pix * 9 + k] = make_int4(oy0 + x0c, oy0 + x1c, oy1 + x0c, oy1 + x1c);
    }
}

#define GATHER4H(dst, basec, ov)                                                       \
    do {                                                                               \
        (dst)[0] = __ldg((const uint4*)((basec) + ((size_t)(bHW + (ov).x)) * Cin));    \
        (dst)[1] = __ldg((const uint4*)((basec) + ((size_t)(bHW + (ov).y)) * Cin));    \
        (dst)[2] = __ldg((const uint4*)((basec) + ((size_t)(bHW + (ov).z)) * Cin));    \
        (dst)[3] = __ldg((const uint4*)((basec) + ((size_t)(bHW + (ov).w)) * Cin));    \
    } while (0)

// combine 4 corners (8 fp16 channels each) with fp32 bilinear weights -> 8 fp16 -> 1 STS.128
static __device__ __forceinline__ void samp_store(__half* dst, int sp, int tk,
                                                  float4 wv, const uint4* t) {
    unsigned r[4];
#pragma unroll
    for (int p = 0; p < 4; p++) {
        float v0 = wv.x * hget(t[0], 2 * p)     + wv.y * hget(t[1], 2 * p)
                 + wv.z * hget(t[2], 2 * p)     + wv.w * hget(t[3], 2 * p);
        float v1 = wv.x * hget(t[0], 2 * p + 1) + wv.y * hget(t[1], 2 * p + 1)
                 + wv.z * hget(t[2], 2 * p + 1) + wv.w * hget(t[3], 2 * p + 1);
        __half2 h = __floats2half2_rn(v0, v1);
        r[p] = *(unsigned*)&h;
    }
    *(uint4*)(dst + sp * KST + tk * 8) = make_uint4(r[0], r[1], r[2], r[3]);
}

// ---------------- kernel 2: pipelined fused sample + FP16 MMA (m16n8k16) ----------------
__global__ void __launch_bounds__(256, 2)
main_kernel(const float* __restrict__ bias,
            float* __restrict__ out) {
    extern __shared__ char dyn[];
    __half* s_s = (__half*)dyn;                          // 2 x 11264 B
    __half* s_w = (__half*)(dyn + 22528);                // 2 x 22528 B

    const int tid  = threadIdx.x;
    const int pix0 = blockIdx.x * 64;
    const int b    = pix0 / HW;
    const int bHW  = b * HW;
    const int hw0  = pix0 - bHW;

    const int lane = tid & 31;
    const int wid  = tid >> 5;
    const int m0   = (wid & 1) * 32;
    const int n0   = (wid >> 1) * 32;
    const int arow = lane >> 2;
    const int acol = lane & 3;
    const int sp   = tid >> 2;            // pixel 0..63
    const int kq   = tid & 3;             // tap phase 0..3

    // hoist this thread's sampling metadata into registers (once)
    const int mbase = (pix0 + sp) * 9;
    int4   mo0 = __ldg(g_meta_off + mbase + kq);
    int4   mo1 = __ldg(g_meta_off + mbase + kq + 4);
    float4 mw0 = __ldg(g_meta_w   + mbase + kq);
    float4 mw1 = __ldg(g_meta_w   + mbase + kq + 4);
    int4   mo2 = make_int4(0, 0, 0, 0);
    float4 mw2 = make_float4(0, 0, 0, 0);
    if (kq == 0) {
        mo2 = __ldg(g_meta_off + mbase + 8);
        mw2 = __ldg(g_meta_w   + mbase + 8);
    }

    // zero sample pad (k 72..79 = 16B per row) in both buffers
    if (tid < 128) {
        int bu = tid >> 6, row = tid & 63;
        *(uint4*)(s_s + bu * SS_BUF_H + row * KST + 72) = make_uint4(0, 0, 0, 0);
    }

    const unsigned dyn_u = (unsigned)__cvta_generic_to_shared(dyn);
    const unsigned ss_u  = dyn_u;
    const unsigned sw_u  = dyn_u + 22528;

    // ldmatrix lane-address constants (byte stride 176)
    const int m2 = lane >> 3;             // matrix index 0..3
    const int l7 = lane & 7;
    // A (samples): mats {(r0,k0),(r8,k0),(r0,k8),(r8,k8)}
    const unsigned aoff0 = (unsigned)((m0 + (m2 & 1) * 8 + l7) * 176 + (m2 >> 1) * 16);
    const unsigned aoff1 = aoff0 + 16 * 176;
    // B (weights): mats {(n0,k0),(n0,k8),(n8,k0),(n8,k8)}
    const unsigned boff0 = (unsigned)((n0 + (m2 >> 1) * 8 + l7) * 176 + (m2 & 1) * 16);
    const unsigned boff1 = boff0 + 16 * 176;

    float acc[2][4][4];
#pragma unroll
    for (int ma = 0; ma < 2; ma++)
#pragma unroll
        for (int na = 0; na < 4; na++)
#pragma unroll
            for (int q = 0; q < 4; q++) acc[ma][na][q] = 0.f;

    // ---- prologue: stage chunk 0 into buffer 0 ----
    {
        const __half* wp = g_wH;
#pragma unroll
        for (int j = 0; j < 5; j++) {
            int idx = tid + j * 256;                 // 0..1279 granules
            int o = idx / 10, g = idx - o * 10;
            cp_async16(sw_u + o * 176 + g * 16, wp + o * KP + g * 8);
        }
        CP_COMMIT();

        uint4 t[4];
        GATHER4H(t, g_xT, mo0);
        samp_store(s_s, sp, kq, mw0, t);
        GATHER4H(t, g_xT, mo1);
        samp_store(s_s, sp, kq + 4, mw1, t);
        if (kq == 0) {
            GATHER4H(t, g_xT, mo2);
            samp_store(s_s, sp, 8, mw2, t);
        }
        CP_WAIT0();
    }
    __syncthreads();

    for (int i = 0; i < NCH; i++) {
        const int cur = i & 1, nxt = cur ^ 1;
        const bool pf = (i + 1) < NCH;

        // ---- 1. prefetch chunk i+1: weights via cp.async, taps into regs ----
        uint4 tp[2][4];
        if (pf) {
            const __half* wp = g_wH + (size_t)(i + 1) * (Cout * KP);
            const unsigned swn_u = sw_u + nxt * 22528;
#pragma unroll
            for (int j = 0; j < 5; j++) {
                int idx = tid + j * 256;
                int o = idx / 10, g = idx - o * 10;
                cp_async16(swn_u + o * 176 + g * 16, wp + o * KP + g * 8);
            }
            CP_COMMIT();
            const __half* basec = g_xT + (i + 1) * CH;
            GATHER4H(tp[0], basec, mo0);
            GATHER4H(tp[1], basec, mo1);
        }

        // ---- 2. MMA on chunk i: 5 k16-steps ----
        {
            const unsigned ssb = ss_u + cur * 11264;
            const unsigned swb = sw_u + cur * 22528;
#pragma unroll
            for (int ks = 0; ks < 5; ks++) {
                const unsigned kof = ks * 32;        // 16 halfs = 32 B
                unsigned a0[4], a1[4], bb0[4], bb1[4];
                LDSM_X4(a0, ssb + aoff0 + kof);
                LDSM_X4(a1, ssb + aoff1 + kof);
                LDSM_X4(bb0, swb + boff0 + kof);
                LDSM_X4(bb1, swb + boff1 + kof);
#pragma unroll
                for (int na = 0; na < 4; na++) {
                    const unsigned* bb = (na < 2) ? bb0 : bb1;
                    unsigned bx = bb[(na & 1) * 2], by = bb[(na & 1) * 2 + 1];
                    asm volatile(
                        "mma.sync.aligned.m16n8k16.row.col.f32.f16.f16.f32 "
                        "{%0,%1,%2,%3}, {%4,%5,%6,%7}, {%8,%9}, {%0,%1,%2,%3};"
                        : "+f"(acc[0][na][0]), "+f"(acc[0][na][1]),
                          "+f"(acc[0][na][2]), "+f"(acc[0][na][3])
                        : "r"(a0[0]), "r"(a0[1]), "r"(a0[2]), "r"(a0[3]),
                          "r"(bx), "r"(by));
                    asm volatile(
                        "mma.sync.aligned.m16n8k16.row.col.f32.f16.f16.f32 "
                        "{%0,%1,%2,%3}, {%4,%5,%6,%7}, {%8,%9}, {%0,%1,%2,%3};"
                        : "+f"(acc[1][na][0]), "+f"(acc[1][na][1]),
                          "+f"(acc[1][na][2]), "+f"(acc[1][na][3])
                        : "r"(a1[0]), "r"(a1[1]), "r"(a1[2]), "r"(a1[3]),
                          "r"(bx), "r"(by));
                }
            }
        }

        // ---- 3. writeback chunk i+1 samples; wait weights; barrier ----
        if (pf) {
            __half* ssn = s_s + nxt * SS_BUF_H;
            samp_store(ssn, sp, kq,     mw0, tp[0]);
            samp_store(ssn, sp, kq + 4, mw1, tp[1]);
            if (kq == 0) {     // inline task tap=8
                const __half* basec = g_xT + (i + 1) * CH;
                uint4 t[4];
                GATHER4H(t, basec, mo2);
                samp_store(ssn, sp, 8, mw2, t);
            }
            CP_WAIT0();
        }
        __syncthreads();
    }

    // ---- epilogue: fp32 bias add + stores ----
#pragma unroll
    for (int ma = 0; ma < 2; ma++) {
        int prow = hw0 + m0 + ma * 16 + arow;
#pragma unroll
        for (int na = 0; na < 4; na++) {
            int o = n0 + na * 8 + 2 * acol;
            float b0 = __ldg(bias + o);
            float b1 = __ldg(bias + o + 1);
            float* p0 = out + ((size_t)b * Cout + o) * HW + prow;
            float* p1 = p0 + HW;
            p0[0] = acc[ma][na][0] + b0;
            p1[0] = acc[ma][na][1] + b1;
            p0[8] = acc[ma][na][2] + b0;
            p1[8] = acc[ma][na][3] + b1;
        }
    }
}

// ---------------- launcher ----------------
extern "C" void kernel_launch(void* const* d_in, const int* in_sizes, int n_in,
                              void* d_out, int out_size) {
    const float* x        = (const float*)d_in[0];
    const float* offset_w = (const float*)d_in[1];
    const float* offset_b = (const float*)d_in[2];
    const float* mod_w    = (const float*)d_in[3];
    const float* mod_b    = (const float*)d_in[4];
    const float* w        = (const float*)d_in[5];
    const float* bias     = (const float*)d_in[6];
    float* out = (float*)d_out;

    const int SMEM = 22528 + 45056;   // 67584 B
    cudaFuncSetAttribute(main_kernel, cudaFuncAttributeMaxDynamicSharedMemorySize, SMEM);

    prep_weights_kernel<<<(NCH * Cout * KP + 255) / 256, 256>>>(w, offset_w, mod_w);
    transpose_kernel<<<dim3(HW / 32, Cin / 32, Bn), 256>>>(x);
    offmask_kernel<<<NPIX / 64, 256>>>(offset_b, mod_b);
    main_kernel<<<NPIX / 64, 256, SMEM>>>(bias, out);
}